// round 3
// baseline (speedup 1.0000x reference)
#include <cuda_runtime.h>
#include <math.h>
#include <stdint.h>

// Problem constants
#define kE   2048
#define kHQ  32
#define kHKV 8
#define kHD  64
#define kB   2
#define kT   2048
#define kM   (kB * kT)          // 4096 rows (B*T)
#define kKVN (2 * kHKV * kHD)   // 1024

// Scratch (device globals — allocation-free per harness rules)
__device__ float g_q[kM * kE];      // q projection  (B*T, E)
__device__ float g_kv[kM * kKVN];   // kv projection (B*T, 1024): k cols [0,512), v cols [512,1024)
__device__ float g_ao[kM * kE];     // attention output (B*T, E)

// ---------------------------------------------------------------------------
// tf32 helpers (legacy mma.sync path; tcgen05 port planned for later rounds)
// ---------------------------------------------------------------------------
__device__ __forceinline__ uint32_t f2tf32(float v) {
    uint32_t r;
    asm("cvt.rna.tf32.f32 %0, %1;" : "=r"(r) : "f"(v));
    return r;
}

__device__ __forceinline__ void split3(float v, uint32_t& hi, uint32_t& lo) {
    uint32_t h = f2tf32(v);
    float hf = __uint_as_float(h);   // tf32 bits are a valid fp32 (low mantissa zeroed)
    lo = f2tf32(v - hf);
    hi = h;
}

__device__ __forceinline__ void mma_tf32(float* d, const uint32_t* a, const uint32_t* b) {
    asm volatile(
        "mma.sync.aligned.m16n8k8.row.col.f32.tf32.tf32.f32 "
        "{%0,%1,%2,%3},{%4,%5,%6,%7},{%8,%9},{%0,%1,%2,%3};\n"
        : "+f"(d[0]), "+f"(d[1]), "+f"(d[2]), "+f"(d[3])
        : "r"(a[0]), "r"(a[1]), "r"(a[2]), "r"(a[3]), "r"(b[0]), "r"(b[1]));
}

// ---------------------------------------------------------------------------
// GEMM: C[M,N] = A[M,K] * W[N,K]^T   (torch Linear), tf32x3 (~fp32 accurate)
// CTA tile 128x128, K-tile 32, 8 warps (warp tile 32x64).
// ---------------------------------------------------------------------------
__global__ __launch_bounds__(256) void gemm_xwT(
        const float* __restrict__ A, const float* __restrict__ W,
        float* __restrict__ C, int N, int K) {
    __shared__ float As[128][36];   // stride 36 == 4 (mod 32): conflict-free frag loads
    __shared__ float Ws[128][36];

    const int tid  = threadIdx.x;
    const int lane = tid & 31;
    const int wid  = tid >> 5;
    const int wm   = wid >> 1;      // 0..3 (32 rows each)
    const int wn   = wid & 1;       // 0..1 (64 cols each)
    const int m0   = blockIdx.y * 128;
    const int n0   = blockIdx.x * 128;

    float acc[2][8][4];
#pragma unroll
    for (int i = 0; i < 2; i++)
#pragma unroll
        for (int j = 0; j < 8; j++)
#pragma unroll
            for (int k = 0; k < 4; k++) acc[i][j][k] = 0.f;

    const int ldrow = tid >> 3;          // 0..31
    const int ldcol = (tid & 7) << 2;    // 0,4,..,28

    for (int kt = 0; kt < K; kt += 32) {
#pragma unroll
        for (int p = 0; p < 4; p++) {
            int row = p * 32 + ldrow;
            *(float4*)&As[row][ldcol] =
                *(const float4*)&A[(size_t)(m0 + row) * K + kt + ldcol];
        }
#pragma unroll
        for (int p = 0; p < 4; p++) {
            int row = p * 32 + ldrow;
            *(float4*)&Ws[row][ldcol] =
                *(const float4*)&W[(size_t)(n0 + row) * K + kt + ldcol];
        }
        __syncthreads();

#pragma unroll
        for (int k8 = 0; k8 < 4; k8++) {
            const int kk = k8 * 8;
            uint32_t ahi[2][4], alo[2][4];
#pragma unroll
            for (int mt = 0; mt < 2; mt++) {
                int r = wm * 32 + mt * 16 + (lane >> 2);
                int c = kk + (lane & 3);
                split3(As[r][c],         ahi[mt][0], alo[mt][0]);
                split3(As[r + 8][c],     ahi[mt][1], alo[mt][1]);
                split3(As[r][c + 4],     ahi[mt][2], alo[mt][2]);
                split3(As[r + 8][c + 4], ahi[mt][3], alo[mt][3]);
            }
            uint32_t bhi[8][2], blo[8][2];
#pragma unroll
            for (int nt = 0; nt < 8; nt++) {
                int r = wn * 64 + nt * 8 + (lane >> 2);
                int c = kk + (lane & 3);
                split3(Ws[r][c],     bhi[nt][0], blo[nt][0]);
                split3(Ws[r][c + 4], bhi[nt][1], blo[nt][1]);
            }
#pragma unroll
            for (int mt = 0; mt < 2; mt++)
#pragma unroll
                for (int nt = 0; nt < 8; nt++) {
                    mma_tf32(acc[mt][nt], alo[mt], bhi[nt]);
                    mma_tf32(acc[mt][nt], ahi[mt], blo[nt]);
                    mma_tf32(acc[mt][nt], ahi[mt], bhi[nt]);
                }
        }
        __syncthreads();
    }

#pragma unroll
    for (int mt = 0; mt < 2; mt++) {
        int r = m0 + wm * 32 + mt * 16 + (lane >> 2);
#pragma unroll
        for (int nt = 0; nt < 8; nt++) {
            int c = n0 + wn * 64 + nt * 8 + ((lane & 3) << 1);
            C[(size_t)r * N + c]           = acc[mt][nt][0];
            C[(size_t)r * N + c + 1]       = acc[mt][nt][1];
            C[(size_t)(r + 8) * N + c]     = acc[mt][nt][2];
            C[(size_t)(r + 8) * N + c + 1] = acc[mt][nt][3];
        }
    }
}

// ---------------------------------------------------------------------------
// Flash attention (causal, GQA): per-CTA 64 query rows of one (b, hq) head.
// 4 warps x 16 rows; online softmax; tf32 mma for QK^T and P*V.
// ---------------------------------------------------------------------------
#define QSTRIDE 68   // == 4 (mod 32)  (Q, K, P buffers)
#define VSTRIDE 72   // == 8 (mod 32)  (V buffer; B-frag pattern conflict-free)
#define ATTN_SMEM ((64 * QSTRIDE * 3 + 64 * VSTRIDE) * 4)

__global__ __launch_bounds__(128) void attn_kernel(
        const float* __restrict__ q, const float* __restrict__ kv,
        float* __restrict__ o_out) {
    extern __shared__ float sm[];
    float* Qs = sm;
    float* Ks = Qs + 64 * QSTRIDE;
    float* Ps = Ks + 64 * QSTRIDE;
    float* Vs = Ps + 64 * QSTRIDE;

    const int tid  = threadIdx.x;
    const int lane = tid & 31;
    const int w    = tid >> 5;
    const int qb   = blockIdx.x;     // query block (64 rows)
    const int bh   = blockIdx.y;     // b * 32 + hq
    const int b    = bh >> 5;
    const int hq   = bh & 31;
    const int hkv  = hq >> 2;        // G = 4

    const int ldrow = tid >> 4;          // 0..7
    const int ldcol = (tid & 15) << 2;   // 0..60

    // Load Q tile, pre-scaled by 1/sqrt(HD)
#pragma unroll
    for (int p = 0; p < 8; p++) {
        int row = p * 8 + ldrow;
        const float4 v = *(const float4*)&q[((size_t)(b * kT + qb * 64 + row)) * kE + hq * kHD + ldcol];
        float4 sv = make_float4(v.x * 0.125f, v.y * 0.125f, v.z * 0.125f, v.w * 0.125f);
        *(float4*)&Qs[row * QSTRIDE + ldcol] = sv;
    }

    float mrow0 = -INFINITY, mrow1 = -INFINITY;
    float lrow0 = 0.f, lrow1 = 0.f;
    float o[8][4];
#pragma unroll
    for (int nt = 0; nt < 8; nt++)
#pragma unroll
        for (int i = 0; i < 4; i++) o[nt][i] = 0.f;

    const int rloc = w * 16 + (lane >> 2);   // thread's row (and rloc+8) within block

    for (int j = 0; j <= qb; j++) {
        // Load K, V tiles (64x64 each)
#pragma unroll
        for (int p = 0; p < 8; p++) {
            int row = p * 8 + ldrow;
            size_t base = ((size_t)(b * kT + j * 64 + row)) * kKVN + hkv * kHD + ldcol;
            *(float4*)&Ks[row * QSTRIDE + ldcol] = *(const float4*)&kv[base];
            *(float4*)&Vs[row * VSTRIDE + ldcol] = *(const float4*)&kv[base + 512];
        }
        __syncthreads();

        // S = Q * K^T  (this warp's 16 rows x 64 cols)
        float s[8][4];
#pragma unroll
        for (int nt = 0; nt < 8; nt++) { s[nt][0] = s[nt][1] = s[nt][2] = s[nt][3] = 0.f; }

#pragma unroll
        for (int k8 = 0; k8 < 8; k8++) {
            const int kk = k8 * 8 + (lane & 3);
            uint32_t a[4];
            a[0] = f2tf32(Qs[rloc * QSTRIDE + kk]);
            a[1] = f2tf32(Qs[(rloc + 8) * QSTRIDE + kk]);
            a[2] = f2tf32(Qs[rloc * QSTRIDE + kk + 4]);
            a[3] = f2tf32(Qs[(rloc + 8) * QSTRIDE + kk + 4]);
#pragma unroll
            for (int nt = 0; nt < 8; nt++) {
                const int kr = nt * 8 + (lane >> 2);
                uint32_t bb[2];
                bb[0] = f2tf32(Ks[kr * QSTRIDE + kk]);
                bb[1] = f2tf32(Ks[kr * QSTRIDE + kk + 4]);
                mma_tf32(s[nt], a, bb);
            }
        }

        // Causal mask on the diagonal block (strict upper triangle -> -inf)
        if (j == qb) {
#pragma unroll
            for (int nt = 0; nt < 8; nt++) {
                int c0 = nt * 8 + ((lane & 3) << 1);
                if (c0     > rloc)     s[nt][0] = -INFINITY;
                if (c0 + 1 > rloc)     s[nt][1] = -INFINITY;
                if (c0     > rloc + 8) s[nt][2] = -INFINITY;
                if (c0 + 1 > rloc + 8) s[nt][3] = -INFINITY;
            }
        }

        // Online softmax: row max (reduce over own 16 vals, then quad shfl)
        float mx0 = -INFINITY, mx1 = -INFINITY;
#pragma unroll
        for (int nt = 0; nt < 8; nt++) {
            mx0 = fmaxf(mx0, fmaxf(s[nt][0], s[nt][1]));
            mx1 = fmaxf(mx1, fmaxf(s[nt][2], s[nt][3]));
        }
        mx0 = fmaxf(mx0, __shfl_xor_sync(0xffffffffu, mx0, 1));
        mx0 = fmaxf(mx0, __shfl_xor_sync(0xffffffffu, mx0, 2));
        mx1 = fmaxf(mx1, __shfl_xor_sync(0xffffffffu, mx1, 1));
        mx1 = fmaxf(mx1, __shfl_xor_sync(0xffffffffu, mx1, 2));

        float mnew0 = fmaxf(mrow0, mx0);
        float mnew1 = fmaxf(mrow1, mx1);
        float alpha0 = __expf(mrow0 - mnew0);   // first iter: exp(-inf) = 0
        float alpha1 = __expf(mrow1 - mnew1);
        mrow0 = mnew0; mrow1 = mnew1;

        float sum0 = 0.f, sum1 = 0.f;
#pragma unroll
        for (int nt = 0; nt < 8; nt++) {
            s[nt][0] = __expf(s[nt][0] - mnew0); sum0 += s[nt][0];
            s[nt][1] = __expf(s[nt][1] - mnew0); sum0 += s[nt][1];
            s[nt][2] = __expf(s[nt][2] - mnew1); sum1 += s[nt][2];
            s[nt][3] = __expf(s[nt][3] - mnew1); sum1 += s[nt][3];
        }
        sum0 += __shfl_xor_sync(0xffffffffu, sum0, 1);
        sum0 += __shfl_xor_sync(0xffffffffu, sum0, 2);
        sum1 += __shfl_xor_sync(0xffffffffu, sum1, 1);
        sum1 += __shfl_xor_sync(0xffffffffu, sum1, 2);

        lrow0 = lrow0 * alpha0 + sum0;
        lrow1 = lrow1 * alpha1 + sum1;

#pragma unroll
        for (int nt = 0; nt < 8; nt++) {
            o[nt][0] *= alpha0; o[nt][1] *= alpha0;
            o[nt][2] *= alpha1; o[nt][3] *= alpha1;
        }

        // C-frag -> A-frag conversion via smem (each warp owns its 16 rows)
#pragma unroll
        for (int nt = 0; nt < 8; nt++) {
            int pc = nt * 8 + ((lane & 3) << 1);
            Ps[rloc * QSTRIDE + pc]           = s[nt][0];
            Ps[rloc * QSTRIDE + pc + 1]       = s[nt][1];
            Ps[(rloc + 8) * QSTRIDE + pc]     = s[nt][2];
            Ps[(rloc + 8) * QSTRIDE + pc + 1] = s[nt][3];
        }
        __syncwarp();

        // O += P * V
#pragma unroll
        for (int k8 = 0; k8 < 8; k8++) {
            const int kk = k8 * 8 + (lane & 3);
            uint32_t a[4];
            a[0] = f2tf32(Ps[rloc * QSTRIDE + kk]);
            a[1] = f2tf32(Ps[(rloc + 8) * QSTRIDE + kk]);
            a[2] = f2tf32(Ps[rloc * QSTRIDE + kk + 4]);
            a[3] = f2tf32(Ps[(rloc + 8) * QSTRIDE + kk + 4]);
#pragma unroll
            for (int nt = 0; nt < 8; nt++) {
                uint32_t bb[2];
                bb[0] = f2tf32(Vs[kk * VSTRIDE + nt * 8 + (lane >> 2)]);
                bb[1] = f2tf32(Vs[(kk + 4) * VSTRIDE + nt * 8 + (lane >> 2)]);
                mma_tf32(o[nt], a, bb);
            }
        }
        __syncthreads();   // protect Ks/Vs before next block load
    }

    // Normalize and write out (same (B,T,HQ,HD) layout as q)
    float inv0 = 1.f / lrow0;
    float inv1 = 1.f / lrow1;
    size_t r0 = (size_t)(b * kT + qb * 64 + rloc) * kE + hq * kHD;
    size_t r1 = (size_t)(b * kT + qb * 64 + rloc + 8) * kE + hq * kHD;
#pragma unroll
    for (int nt = 0; nt < 8; nt++) {
        int c = nt * 8 + ((lane & 3) << 1);
        o_out[r0 + c]     = o[nt][0] * inv0;
        o_out[r0 + c + 1] = o[nt][1] * inv0;
        o_out[r1 + c]     = o[nt][2] * inv1;
        o_out[r1 + c + 1] = o[nt][3] * inv1;
    }
}

// ---------------------------------------------------------------------------
// Launch: q-proj, kv-proj, attention, o-proj (sequential on default stream)
// ---------------------------------------------------------------------------
extern "C" void kernel_launch(void* const* d_in, const int* in_sizes, int n_in,
                              void* d_out, int out_size) {
    (void)in_sizes; (void)n_in; (void)out_size;
    const float* x   = (const float*)d_in[0];
    const float* Wq  = (const float*)d_in[1];
    const float* Wkv = (const float*)d_in[2];
    const float* Wo  = (const float*)d_in[3];
    float* out = (float*)d_out;

    float *q, *kvb, *ao;
    cudaGetSymbolAddress((void**)&q,   g_q);
    cudaGetSymbolAddress((void**)&kvb, g_kv);
    cudaGetSymbolAddress((void**)&ao,  g_ao);

    cudaFuncSetAttribute(attn_kernel,
                         cudaFuncAttributeMaxDynamicSharedMemorySize, ATTN_SMEM);

    dim3 blk(256);
    gemm_xwT<<<dim3(kE / 128,   kM / 128), blk>>>(x,  Wq,  q,   kE,   kE);
    gemm_xwT<<<dim3(kKVN / 128, kM / 128), blk>>>(x,  Wkv, kvb, kKVN, kE);
    attn_kernel<<<dim3(kT / 64, kB * kHQ), dim3(128), ATTN_SMEM>>>(q, kvb, ao);
    gemm_xwT<<<dim3(kE / 128,   kM / 128), blk>>>(ao, Wo,  out, kE,   kE);
}